// round 15
// baseline (speedup 1.0000x reference)
#include <cuda_runtime.h>
#include <cuda_fp16.h>

#define TPB    192        // one thread per 8 floats of a 1536-float row
#define NCOLS  192
#define BAND   16         // output rows per block
#define HH     384
#define ROWF   1536       // W*C floats per row
#define NBANDS (HH / BAND)
#define PFDIST 8          // prefetch distance in rows (one full unroll group)

static __device__ __forceinline__ int hrefl(int h) {
    // reflect-101 along height; valid for |h| < 2*HH-1 (we use [-2, HH+9])
    h = (h < 0) ? -h : h;
    return (h >= HH) ? (2 * HH - 2 - h) : h;
}

// Gaussian taps for ksize=5, sigma=1.1 (OpenCV default), normalized.
#define C0 0.07076630f    /* w[0] = w[4] */
#define C1 0.24446028f    /* w[1] = w[3] */
#define C2 0.36954642f    /* w[2]        */

struct F8 { float v[8]; };
struct H8 { __half2 h[4]; };   // fp16-compressed hb row (8 values, 16 bytes)

static __device__ __forceinline__ H8 packF8(const F8& f) {
    H8 o;
    #pragma unroll
    for (int j = 0; j < 4; j++)
        o.h[j] = __floats2half2_rn(f.v[2 * j], f.v[2 * j + 1]);
    return o;
}

// Load row h and horizontally blur this thread's 8 floats (flats 8g..8g+7).
// Intra-warp halo via shuffles; warp-edge lanes load their 6-float halo;
// image width edges fold reflect-101 into a register permutation.
static __device__ __forceinline__ F8 hb_row(
    const float* __restrict__ ib, int h, int g, int lane)
{
    const float* __restrict__ rp = ib + (long)hrefl(h) * ROWF + 8 * g;
    float4 Cb = *(const float4*)(rp);       // flats 8g   .. 8g+3
    float4 Db = *(const float4*)(rp + 4);   // flats 8g+4 .. 8g+7

    // e[k] = flat(8g - 6 + k), k = 0..19
    float e0  = __shfl_up_sync(0xffffffffu, Cb.z, 1);
    float e1  = __shfl_up_sync(0xffffffffu, Cb.w, 1);
    float e2  = __shfl_up_sync(0xffffffffu, Db.x, 1);
    float e3  = __shfl_up_sync(0xffffffffu, Db.y, 1);
    float e4  = __shfl_up_sync(0xffffffffu, Db.z, 1);
    float e5  = __shfl_up_sync(0xffffffffu, Db.w, 1);
    float e14 = __shfl_down_sync(0xffffffffu, Cb.x, 1);
    float e15 = __shfl_down_sync(0xffffffffu, Cb.y, 1);
    float e16 = __shfl_down_sync(0xffffffffu, Cb.z, 1);
    float e17 = __shfl_down_sync(0xffffffffu, Cb.w, 1);
    float e18 = __shfl_down_sync(0xffffffffu, Db.x, 1);
    float e19 = __shfl_down_sync(0xffffffffu, Db.y, 1);

    if (lane == 0 && g > 0) {
        float2 a = *(const float2*)(rp - 6);
        float4 b = *(const float4*)(rp - 4);
        e0 = a.x; e1 = a.y; e2 = b.x; e3 = b.y; e4 = b.z; e5 = b.w;
    }
    if (lane == 31 && g < NCOLS - 1) {
        float4 b = *(const float4*)(rp + 8);
        float2 a = *(const float2*)(rp + 12);
        e14 = b.x; e15 = b.y; e16 = b.z; e17 = b.w; e18 = a.x; e19 = a.y;
    }
    if (g == 0) {            // flats -6..-1 -> reflected {6,7,8,3,4,5}
        e0 = Db.z; e1 = Db.w; e2 = e14; e3 = Cb.w; e4 = Db.x; e5 = Db.y;
    }
    if (g == NCOLS - 1) {    // flats 1536..1541 -> {1530,1531,1532,1527,1528,1529}
        e14 = Cb.z; e15 = Cb.w; e16 = Db.x; e17 = e5; e18 = Cb.x; e19 = Cb.y;
    }

    const float e6 = Cb.x, e7 = Cb.y, e8 = Cb.z, e9 = Cb.w;
    const float e10 = Db.x, e11 = Db.y, e12 = Db.z, e13 = Db.w;

    // Horizontal taps at flat offsets {-6,-3,0,+3,+6}.
    F8 o;
    o.v[0] = C0 * (e0 + e12) + C1 * (e3  + e9)  + C2 * e6;
    o.v[1] = C0 * (e1 + e13) + C1 * (e4  + e10) + C2 * e7;
    o.v[2] = C0 * (e2 + e14) + C1 * (e5  + e11) + C2 * e8;
    o.v[3] = C0 * (e3 + e15) + C1 * (e6  + e12) + C2 * e9;
    o.v[4] = C0 * (e4 + e16) + C1 * (e7  + e13) + C2 * e10;
    o.v[5] = C0 * (e5 + e17) + C1 * (e8  + e14) + C2 * e11;
    o.v[6] = C0 * (e6 + e18) + C1 * (e9  + e15) + C2 * e12;
    o.v[7] = C0 * (e7 + e19) + C1 * (e10 + e16) + C2 * e13;
    return o;
}

__global__ void __launch_bounds__(TPB, 4)
gauss5_kernel(const float* __restrict__ x, float* __restrict__ y)
{
    const int t    = threadIdx.x;
    const int lane = t & 31;
    const int h0   = blockIdx.x * BAND;
    const long img = blockIdx.y;

    const float* __restrict__ ib = x + img * (long)(HH * ROWF);
    float*       __restrict__ ob = y + img * (long)(HH * ROWF) + 8 * t;

    // Warp-chunk base for L2 prefetch: lanes 0..7 cover the warp's 1KB row
    // chunk at 128B strides.
    const int pfoff = (t & ~31) * 8 + (lane << 5);

    // Prologue prefetch: rows h0+2 .. h0+2+PFDIST-1 (one unroll group ahead).
    if (lane < 8) {
        #pragma unroll
        for (int q = 0; q < PFDIST; q++) {
            const float* pf = ib + (long)hrefl(h0 + 2 + q) * ROWF + pfoff;
            asm volatile("prefetch.global.L2 [%0];" :: "l"(pf));
        }
    }

    // 4-row sliding window of horizontally-blurred values, fp16-compressed.
    H8 w0 = packF8(hb_row(ib, h0 - 2, t, lane));
    H8 w1 = packF8(hb_row(ib, h0 - 1, t, lane));
    H8 w2 = packF8(hb_row(ib, h0,     t, lane));
    H8 w3 = packF8(hb_row(ib, h0 + 1, t, lane));

    // unroll 8: lets ptxas batch independent row loads per group.
    #pragma unroll 8
    for (int r = 0; r < BAND; r++) {
        // Register-free look-ahead: pull row r+2+PFDIST into L2.
        if (lane < 8) {
            const float* pf = ib + (long)hrefl(h0 + r + 2 + PFDIST) * ROWF + pfoff;
            asm volatile("prefetch.global.L2 [%0];" :: "l"(pf));
        }

        F8 w4 = hb_row(ib, h0 + r + 2, t, lane);

        // Vertical pass: unpack window to fp32, combine in fp32.
        float o[8];
        #pragma unroll
        for (int j = 0; j < 4; j++) {
            float2 f0 = __half22float2(w0.h[j]);
            float2 f1 = __half22float2(w1.h[j]);
            float2 f2 = __half22float2(w2.h[j]);
            float2 f3 = __half22float2(w3.h[j]);
            o[2 * j]     = C0 * (f0.x + w4.v[2 * j])     + C1 * (f1.x + f3.x) + C2 * f2.x;
            o[2 * j + 1] = C0 * (f0.y + w4.v[2 * j + 1]) + C1 * (f1.y + f3.y) + C2 * f2.y;
        }

        float* op = ob + (long)(h0 + r) * ROWF;
        *(float4*)op       = make_float4(o[0], o[1], o[2], o[3]);
        *(float4*)(op + 4) = make_float4(o[4], o[5], o[6], o[7]);

        w0 = w1; w1 = w2; w2 = w3; w3 = packF8(w4);
    }
}

extern "C" void kernel_launch(void* const* d_in, const int* in_sizes, int n_in,
                              void* d_out, int out_size)
{
    const float* x = (const float*)d_in[0];
    float* y = (float*)d_out;
    const int batch = in_sizes[0] / (HH * ROWF);   // 64
    dim3 grid(NBANDS, batch);
    gauss5_kernel<<<grid, TPB>>>(x, y);
}

// round 16
// speedup vs baseline: 1.0764x; 1.0764x over previous
#include <cuda_runtime.h>
#include <cuda_fp16.h>

#define TPB    192        // one thread per 8 floats of a 1536-float row
#define NCOLS  192
#define BAND   16         // output rows per block
#define HH     384
#define ROWF   1536       // W*C floats per row
#define NBANDS (HH / BAND)
#define PFDIST 4          // prefetch distance in rows (measured optimum)

static __device__ __forceinline__ int hrefl(int h) {
    // reflect-101 along height; valid for |h| < 2*HH-1 (we use [-2, HH+5])
    h = (h < 0) ? -h : h;
    return (h >= HH) ? (2 * HH - 2 - h) : h;
}

// Gaussian taps for ksize=5, sigma=1.1 (OpenCV default), normalized.
#define C0 0.07076630f    /* w[0] = w[4] */
#define C1 0.24446028f    /* w[1] = w[3] */
#define C2 0.36954642f    /* w[2]        */

struct F8 { float v[8]; };
struct H8 { __half2 h[4]; };   // fp16-compressed hb row (8 values, 16 bytes)

static __device__ __forceinline__ H8 packF8(const F8& f) {
    H8 o;
    #pragma unroll
    for (int j = 0; j < 4; j++)
        o.h[j] = __floats2half2_rn(f.v[2 * j], f.v[2 * j + 1]);
    return o;
}

// Load row h and horizontally blur this thread's 8 floats (flats 8g..8g+7).
// Intra-warp halo via shuffles; warp-edge lanes load their 6-float halo;
// image width edges fold reflect-101 into a register permutation.
static __device__ __forceinline__ F8 hb_row(
    const float* __restrict__ ib, int h, int g, int lane)
{
    const float* __restrict__ rp = ib + (long)hrefl(h) * ROWF + 8 * g;
    float4 Cb = *(const float4*)(rp);       // flats 8g   .. 8g+3
    float4 Db = *(const float4*)(rp + 4);   // flats 8g+4 .. 8g+7

    // e[k] = flat(8g - 6 + k), k = 0..19
    float e0  = __shfl_up_sync(0xffffffffu, Cb.z, 1);
    float e1  = __shfl_up_sync(0xffffffffu, Cb.w, 1);
    float e2  = __shfl_up_sync(0xffffffffu, Db.x, 1);
    float e3  = __shfl_up_sync(0xffffffffu, Db.y, 1);
    float e4  = __shfl_up_sync(0xffffffffu, Db.z, 1);
    float e5  = __shfl_up_sync(0xffffffffu, Db.w, 1);
    float e14 = __shfl_down_sync(0xffffffffu, Cb.x, 1);
    float e15 = __shfl_down_sync(0xffffffffu, Cb.y, 1);
    float e16 = __shfl_down_sync(0xffffffffu, Cb.z, 1);
    float e17 = __shfl_down_sync(0xffffffffu, Cb.w, 1);
    float e18 = __shfl_down_sync(0xffffffffu, Db.x, 1);
    float e19 = __shfl_down_sync(0xffffffffu, Db.y, 1);

    if (lane == 0 && g > 0) {
        float2 a = *(const float2*)(rp - 6);
        float4 b = *(const float4*)(rp - 4);
        e0 = a.x; e1 = a.y; e2 = b.x; e3 = b.y; e4 = b.z; e5 = b.w;
    }
    if (lane == 31 && g < NCOLS - 1) {
        float4 b = *(const float4*)(rp + 8);
        float2 a = *(const float2*)(rp + 12);
        e14 = b.x; e15 = b.y; e16 = b.z; e17 = b.w; e18 = a.x; e19 = a.y;
    }
    if (g == 0) {            // flats -6..-1 -> reflected {6,7,8,3,4,5}
        e0 = Db.z; e1 = Db.w; e2 = e14; e3 = Cb.w; e4 = Db.x; e5 = Db.y;
    }
    if (g == NCOLS - 1) {    // flats 1536..1541 -> {1530,1531,1532,1527,1528,1529}
        e14 = Cb.z; e15 = Cb.w; e16 = Db.x; e17 = e5; e18 = Cb.x; e19 = Cb.y;
    }

    const float e6 = Cb.x, e7 = Cb.y, e8 = Cb.z, e9 = Cb.w;
    const float e10 = Db.x, e11 = Db.y, e12 = Db.z, e13 = Db.w;

    // Horizontal taps at flat offsets {-6,-3,0,+3,+6}.
    F8 o;
    o.v[0] = C0 * (e0 + e12) + C1 * (e3  + e9)  + C2 * e6;
    o.v[1] = C0 * (e1 + e13) + C1 * (e4  + e10) + C2 * e7;
    o.v[2] = C0 * (e2 + e14) + C1 * (e5  + e11) + C2 * e8;
    o.v[3] = C0 * (e3 + e15) + C1 * (e6  + e12) + C2 * e9;
    o.v[4] = C0 * (e4 + e16) + C1 * (e7  + e13) + C2 * e10;
    o.v[5] = C0 * (e5 + e17) + C1 * (e8  + e14) + C2 * e11;
    o.v[6] = C0 * (e6 + e18) + C1 * (e9  + e15) + C2 * e12;
    o.v[7] = C0 * (e7 + e19) + C1 * (e10 + e16) + C2 * e13;
    return o;
}

__global__ void __launch_bounds__(TPB, 4)
gauss5_kernel(const float* __restrict__ x, float* __restrict__ y)
{
    const int t    = threadIdx.x;
    const int lane = t & 31;
    const int h0   = blockIdx.x * BAND;
    const long img = blockIdx.y;

    const float* __restrict__ ib = x + img * (long)(HH * ROWF);
    float*       __restrict__ ob = y + img * (long)(HH * ROWF) + 8 * t;

    // Warp-chunk base for L2 prefetch: lanes 0..7 cover the warp's 1KB row
    // chunk at 128B strides.
    const int pfoff = (t & ~31) * 8 + (lane << 5);

    // Prologue prefetch: rows h0+2 .. h0+2+PFDIST-1.
    if (lane < 8) {
        #pragma unroll
        for (int q = 0; q < PFDIST; q++) {
            const float* pf = ib + (long)hrefl(h0 + 2 + q) * ROWF + pfoff;
            asm volatile("prefetch.global.L2 [%0];" :: "l"(pf));
        }
    }

    // 4-row sliding window of horizontally-blurred values, fp16-compressed.
    H8 w0 = packF8(hb_row(ib, h0 - 2, t, lane));
    H8 w1 = packF8(hb_row(ib, h0 - 1, t, lane));
    H8 w2 = packF8(hb_row(ib, h0,     t, lane));
    H8 w3 = packF8(hb_row(ib, h0 + 1, t, lane));

    // unroll 8: lets ptxas batch independent row loads per group.
    #pragma unroll 8
    for (int r = 0; r < BAND; r++) {
        // Register-free look-ahead: pull row r+2+PFDIST into L2.
        if (lane < 8) {
            const float* pf = ib + (long)hrefl(h0 + r + 2 + PFDIST) * ROWF + pfoff;
            asm volatile("prefetch.global.L2 [%0];" :: "l"(pf));
        }

        F8 w4 = hb_row(ib, h0 + r + 2, t, lane);

        // Vertical pass: unpack window to fp32, combine in fp32.
        float o[8];
        #pragma unroll
        for (int j = 0; j < 4; j++) {
            float2 f0 = __half22float2(w0.h[j]);
            float2 f1 = __half22float2(w1.h[j]);
            float2 f2 = __half22float2(w2.h[j]);
            float2 f3 = __half22float2(w3.h[j]);
            o[2 * j]     = C0 * (f0.x + w4.v[2 * j])     + C1 * (f1.x + f3.x) + C2 * f2.x;
            o[2 * j + 1] = C0 * (f0.y + w4.v[2 * j + 1]) + C1 * (f1.y + f3.y) + C2 * f2.y;
        }

        // Evict-first streaming stores: output is never re-read; keep L2
        // capacity for the inter-band input halo rows.
        float* op = ob + (long)(h0 + r) * ROWF;
        __stcs((float4*)op,       make_float4(o[0], o[1], o[2], o[3]));
        __stcs((float4*)(op + 4), make_float4(o[4], o[5], o[6], o[7]));

        w0 = w1; w1 = w2; w2 = w3; w3 = packF8(w4);
    }
}

extern "C" void kernel_launch(void* const* d_in, const int* in_sizes, int n_in,
                              void* d_out, int out_size)
{
    const float* x = (const float*)d_in[0];
    float* y = (float*)d_out;
    const int batch = in_sizes[0] / (HH * ROWF);   // 64
    dim3 grid(NBANDS, batch);
    gauss5_kernel<<<grid, TPB>>>(x, y);
}